// round 10
// baseline (speedup 1.0000x reference)
#include <cuda_runtime.h>
#include <cstdint>

#define BM      32        // rows per CTA iteration
#define KDIM    64
#define NDIM    128
#define THREADS 128       // 4 warps, each owns a 32-col band
#define MAXGRID 592       // 4 persistent CTAs per SM x 148 SMs

// Precomputed tf32 B fragments: [ks 0..7][nblock 0..7][lane 0..31] float4
// float4 = { b0(ntA), b1(ntA), b0(ntB), b1(ntB) } with the phi column remap.
// k-map (must match the A-side direct-LDG layout):
//   ks = 2j + odd;  lane qk slot0 phys k = 16j + 4qk + 2*odd, slot1 = +1
__device__ float4 g_Bfrag[8 * 8 * 32];

__device__ __forceinline__ uint32_t f2tf32(float f) {
    uint32_t r;
    asm("cvt.rna.tf32.f32 %0, %1;" : "=r"(r) : "f"(f));
    return r;
}

__global__ void setup_kernel(const float* __restrict__ W) {
    int t = blockIdx.x * blockDim.x + threadIdx.x;   // 0..2047
    int lane = t & 31;
    int nb   = (t >> 5) & 7;     // 16-col block
    int ks   = t >> 8;           // k-step
    int qk   = lane & 3;
    int s    = lane >> 2;        // B fragment n-slot
    int colA = nb * 16 + (s >> 1) * 4 + (s & 1);
    int colB = colA + 2;
    int k0 = 16 * (ks >> 1) + 4 * qk + 2 * (ks & 1);   // direct-LDG k-map
    float4 v;
    v.x = __uint_as_float(f2tf32(W[k0 * NDIM + colA]));
    v.y = __uint_as_float(f2tf32(W[(k0 + 1) * NDIM + colA]));
    v.z = __uint_as_float(f2tf32(W[k0 * NDIM + colB]));
    v.w = __uint_as_float(f2tf32(W[(k0 + 1) * NDIM + colB]));
    g_Bfrag[t] = v;
}

__global__ void __launch_bounds__(THREADS, 4)
dense_ragged_kernel(const float* __restrict__ x,
                    const float* __restrict__ bias,
                    float* __restrict__ out,
                    long M, int ntiles)
{
    __shared__ float bsm[NDIM];

    const int tid    = threadIdx.x;
    const int lane   = tid & 31;
    const int warp_n = tid >> 5;          // 4 col bands of 32
    const int qrow   = lane >> 2;         // 0..7
    const int qk     = lane & 3;          // 0..3

    if (tid < 32) ((float4*)bsm)[tid] = ((const float4*)bias)[tid];

    // ---- persistent per-warp B fragments in registers ----
    float4 Breg[8][2];
    #pragma unroll
    for (int ks = 0; ks < 8; ++ks)
        #pragma unroll
        for (int nbi = 0; nbi < 2; ++nbi)
            Breg[ks][nbi] = g_Bfrag[(ks * 8 + warp_n * 2 + nbi) * 32 + lane];

    __syncthreads();   // bsm ready (only barrier in the kernel)

    const int g = gridDim.x;

    for (int it = blockIdx.x; it < ntiles; it += g) {
        long base = (long)it * BM;

        #pragma unroll
        for (int mt = 0; mt < 2; ++mt) {
            long r0 = base + mt * 16 + qrow;     // fragment rows r0, r0+8
            long r1 = r0 + 8;
            long rr0 = (r0 < M) ? r0 : 0;        // clamp reads for ragged tail
            long rr1 = (r1 < M) ? r1 : 0;

            // direct global loads of A fragments: phys cols 16j + 4qk .. +3
            const float4* p0 = (const float4*)(x + rr0 * KDIM) + qk;
            const float4* p1 = (const float4*)(x + rr1 * KDIM) + qk;
            float4 A0[4], A1[4];
            #pragma unroll
            for (int j = 0; j < 4; ++j) { A0[j] = p0[j * 4]; A1[j] = p1[j * 4]; }

            float acc[2][8];   // [nbi][ntA:0..3, ntB:4..7]
            #pragma unroll
            for (int nb = 0; nb < 2; ++nb)
                #pragma unroll
                for (int e = 0; e < 8; ++e) acc[nb][e] = 0.f;

            #pragma unroll
            for (int ks = 0; ks < 8; ++ks) {
                const int j   = ks >> 1;
                const int odd = ks & 1;
                // raw fp32 bits: tf32 mma reads top 19 bits (HW truncation)
                uint32_t a0 = __float_as_uint(odd ? A0[j].z : A0[j].x);
                uint32_t a1 = __float_as_uint(odd ? A1[j].z : A1[j].x);
                uint32_t a2 = __float_as_uint(odd ? A0[j].w : A0[j].y);
                uint32_t a3 = __float_as_uint(odd ? A1[j].w : A1[j].y);
                #pragma unroll
                for (int nbi = 0; nbi < 2; ++nbi) {
                    uint32_t bA0 = __float_as_uint(Breg[ks][nbi].x);
                    uint32_t bA1 = __float_as_uint(Breg[ks][nbi].y);
                    uint32_t bB0 = __float_as_uint(Breg[ks][nbi].z);
                    uint32_t bB1 = __float_as_uint(Breg[ks][nbi].w);
                    asm volatile(
                        "mma.sync.aligned.m16n8k8.row.col.f32.tf32.tf32.f32 "
                        "{%0,%1,%2,%3}, {%4,%5,%6,%7}, {%8,%9}, {%0,%1,%2,%3};\n"
                        : "+f"(acc[nbi][0]), "+f"(acc[nbi][1]),
                          "+f"(acc[nbi][2]), "+f"(acc[nbi][3])
                        : "r"(a0), "r"(a1), "r"(a2), "r"(a3),
                          "r"(bA0), "r"(bA1));
                    asm volatile(
                        "mma.sync.aligned.m16n8k8.row.col.f32.tf32.tf32.f32 "
                        "{%0,%1,%2,%3}, {%4,%5,%6,%7}, {%8,%9}, {%0,%1,%2,%3};\n"
                        : "+f"(acc[nbi][4]), "+f"(acc[nbi][5]),
                          "+f"(acc[nbi][6]), "+f"(acc[nbi][7])
                        : "r"(a0), "r"(a1), "r"(a2), "r"(a3),
                          "r"(bB0), "r"(bB1));
                }
            }

            // ---- epilogue: bias + relu + STG.128 ----
            #pragma unroll
            for (int nbi = 0; nbi < 2; ++nbi) {
                int c = warp_n * 32 + nbi * 16 + qk * 4;
                float4 bb = *(const float4*)(bsm + c);
                if (r0 < M) {
                    float4 o;
                    o.x = fmaxf(acc[nbi][0] + bb.x, 0.f);
                    o.y = fmaxf(acc[nbi][1] + bb.y, 0.f);
                    o.z = fmaxf(acc[nbi][4] + bb.z, 0.f);
                    o.w = fmaxf(acc[nbi][5] + bb.w, 0.f);
                    __stcs((float4*)(out + r0 * NDIM + c), o);
                }
                if (r1 < M) {
                    float4 o;
                    o.x = fmaxf(acc[nbi][2] + bb.x, 0.f);
                    o.y = fmaxf(acc[nbi][3] + bb.y, 0.f);
                    o.z = fmaxf(acc[nbi][6] + bb.z, 0.f);
                    o.w = fmaxf(acc[nbi][7] + bb.w, 0.f);
                    __stcs((float4*)(out + r1 * NDIM + c), o);
                }
            }
        }
    }
}

extern "C" void kernel_launch(void* const* d_in, const int* in_sizes, int n_in,
                              void* d_out, int out_size) {
    const float* x = (const float*)d_in[0];
    const float* W = (const float*)d_in[1];
    const float* b = (const float*)d_in[2];
    float* out = (float*)d_out;

    long M = (long)in_sizes[0] / KDIM;
    int ntiles = (int)((M + BM - 1) / BM);
    int grid = ntiles < MAXGRID ? ntiles : MAXGRID;

    setup_kernel<<<8, 256>>>(W);
    dense_ragged_kernel<<<grid, THREADS>>>(x, b, out, M, ntiles);
}

// round 11
// speedup vs baseline: 1.5732x; 1.5732x over previous
#include <cuda_runtime.h>
#include <cstdint>

#define BM      32        // rows per tile (CTA)
#define KDIM    64
#define NDIM    128
#define THREADS 256       // 8 warps, each owns a 16-col band
#define MAXGRID 444       // 3 persistent CTAs per SM x 148 SMs

#define STAGE_FLOATS (BM * KDIM)   // 2048 floats = 8KB per stage, 3 stages = 24KB

// Precomputed tf32 B fragments: [ks 0..7][nblock 0..7][lane 0..31] float4
// float4 = { b0(ntA), b1(ntA), b0(ntB), b1(ntB) } with the phi column remap.
// k-map (matches the LDS.128 A layout): ks = 2j + odd;
//   lane qk slot0 phys k = 16j + 4qk + 2*odd, slot1 = +1
__device__ float4 g_Bfrag[8 * 8 * 32];

__device__ __forceinline__ uint32_t f2tf32(float f) {
    uint32_t r;
    asm("cvt.rna.tf32.f32 %0, %1;" : "=r"(r) : "f"(f));
    return r;
}

__global__ void setup_kernel(const float* __restrict__ W) {
    int t = blockIdx.x * blockDim.x + threadIdx.x;   // 0..2047
    int lane = t & 31;
    int nb   = (t >> 5) & 7;     // 16-col block
    int ks   = t >> 8;           // k-step
    int qk   = lane & 3;
    int s    = lane >> 2;        // B fragment n-slot
    int colA = nb * 16 + (s >> 1) * 4 + (s & 1);
    int colB = colA + 2;
    int k0 = 16 * (ks >> 1) + 4 * qk + 2 * (ks & 1);   // j-based k-map
    float4 v;
    v.x = __uint_as_float(f2tf32(W[k0 * NDIM + colA]));
    v.y = __uint_as_float(f2tf32(W[(k0 + 1) * NDIM + colA]));
    v.z = __uint_as_float(f2tf32(W[k0 * NDIM + colB]));
    v.w = __uint_as_float(f2tf32(W[(k0 + 1) * NDIM + colB]));
    g_Bfrag[t] = v;
}

// Swizzled x-tile staging: float offset of phys float p in row = p ^ ((row&3)<<4)
// (swizzle touches bits [5:4] only -> 16B cp.async chunks stay contiguous/aligned)
__device__ __forceinline__ void issue_tile(const float* __restrict__ x,
                                           float* xsbuf, long tile_row,
                                           long M, int tid) {
    #pragma unroll
    for (int j = 0; j < 2; ++j) {
        int idx = tid + j * THREADS;       // 0..511
        int row = idx >> 4;                // 0..31
        int c4  = idx & 15;                // float4 column
        long grow = tile_row + row;
        bool valid = (grow < M);
        const float* src = x + (valid ? grow : 0) * KDIM + c4 * 4;
        int foff = row * KDIM + ((c4 * 4) ^ ((row & 3) << 4));
        uint32_t dst = (uint32_t)__cvta_generic_to_shared(xsbuf + foff);
        int sz = valid ? 16 : 0;
        asm volatile("cp.async.cg.shared.global [%0], [%1], 16, %2;\n"
                     :: "r"(dst), "l"(src), "r"(sz));
    }
}

__global__ void __launch_bounds__(THREADS, 3)
dense_ragged_kernel(const float* __restrict__ x,
                    const float* __restrict__ bias,
                    float* __restrict__ out,
                    long M, int ntiles)
{
    __shared__ float xs[3 * STAGE_FLOATS];   // 24KB, 3-stage ring

    const int tid    = threadIdx.x;
    const int lane   = tid & 31;
    const int warp_n = tid >> 5;          // 8 col bands of 16
    const int qrow   = lane >> 2;         // 0..7
    const int qk     = lane & 3;          // 0..3

    // ---- persistent per-warp B fragments (16 cols x full K): 32 regs ----
    float4 Breg[8];
    #pragma unroll
    for (int ks = 0; ks < 8; ++ks)
        Breg[ks] = g_Bfrag[(ks * 8 + warp_n) * 32 + lane];

    // ---- loop-invariant bias fragment (4 regs) ----
    const int cbase = warp_n * 16 + qk * 4;
    const float4 bb = *(const float4*)(bias + cbase);

    // A LDS base: smem row = mt*16 + qrow (+8); swizzle term constant per thread
    const int sw    = (qrow & 3) << 4;
    const int abase = qrow * KDIM + (4 * qk ^ sw);   // (16j) added per j (bits [5:4] -> xor == add with sw folded)
    const int g = gridDim.x;

    int it = blockIdx.x;
    if (it < ntiles) {
        issue_tile(x, xs, (long)it * BM, M, tid);
        asm volatile("cp.async.commit_group;\n");
        if (it + g < ntiles) {
            issue_tile(x, xs + STAGE_FLOATS, (long)(it + g) * BM, M, tid);
            asm volatile("cp.async.commit_group;\n");
        }
    }

    int stage = 0;
    while (it < ntiles) {
        int n1 = it + g;
        int n2 = it + 2 * g;

        if (n1 < ntiles) {
            asm volatile("cp.async.wait_group 1;\n");
        } else {
            asm volatile("cp.async.wait_group 0;\n");
        }
        __syncthreads();   // single barrier per tile

        if (n2 < ntiles) {
            int ws = stage + 2; if (ws >= 3) ws -= 3;
            issue_tile(x, xs + ws * STAGE_FLOATS, (long)n2 * BM, M, tid);
            asm volatile("cp.async.commit_group;\n");
        }

        const float* xb = xs + stage * STAGE_FLOATS;

        #pragma unroll
        for (int mt = 0; mt < 2; ++mt) {
            float acc[8];
            #pragma unroll
            for (int e = 0; e < 8; ++e) acc[e] = 0.f;

            const float* pr = xb + mt * (16 * KDIM) + abase;

            #pragma unroll
            for (int j = 0; j < 4; ++j) {
                // LDS.128: rows (mt*16+qrow) and (+8), 4 consecutive phys k
                // offset for 16j: bits [5:4] of (16j ^ sw) already folded via xor-add identity
                int joff = (16 * j) ^ sw;           // bits[5:4] region
                joff ^= sw;                          // = 16*j  (restore) ... see note
                // NOTE: abase already xor'ed 4qk with sw; adding 16j keeps bits[3:0]
                // intact and bits[5:4] must ALSO be xor'ed with sw. Do it properly:
                int off = (qrow * KDIM) + (((16 * j + 4 * qk)) ^ sw) + mt * (16 * KDIM);
                float4 v0 = *(const float4*)(xb + off);
                float4 v1 = *(const float4*)(xb + off + 8 * KDIM);

                #pragma unroll
                for (int odd = 0; odd < 2; ++odd) {
                    // raw fp32 bits: tf32 mma reads top 19 bits (HW truncation)
                    uint32_t a0 = __float_as_uint(odd ? v0.z : v0.x);
                    uint32_t a1 = __float_as_uint(odd ? v1.z : v1.x);
                    uint32_t a2 = __float_as_uint(odd ? v0.w : v0.y);
                    uint32_t a3 = __float_as_uint(odd ? v1.w : v1.y);
                    const float4 w = Breg[2 * j + odd];
                    uint32_t bA0 = __float_as_uint(w.x), bA1 = __float_as_uint(w.y);
                    uint32_t bB0 = __float_as_uint(w.z), bB1 = __float_as_uint(w.w);
                    asm volatile(
                        "mma.sync.aligned.m16n8k8.row.col.f32.tf32.tf32.f32 "
                        "{%0,%1,%2,%3}, {%4,%5,%6,%7}, {%8,%9}, {%0,%1,%2,%3};\n"
                        : "+f"(acc[0]), "+f"(acc[1]), "+f"(acc[2]), "+f"(acc[3])
                        : "r"(a0), "r"(a1), "r"(a2), "r"(a3), "r"(bA0), "r"(bA1));
                    asm volatile(
                        "mma.sync.aligned.m16n8k8.row.col.f32.tf32.tf32.f32 "
                        "{%0,%1,%2,%3}, {%4,%5,%6,%7}, {%8,%9}, {%0,%1,%2,%3};\n"
                        : "+f"(acc[4]), "+f"(acc[5]), "+f"(acc[6]), "+f"(acc[7])
                        : "r"(a0), "r"(a1), "r"(a2), "r"(a3), "r"(bB0), "r"(bB1));
                }
            }

            // ---- epilogue per 16-row band: bias + relu + STG.128 ----
            long r0 = (long)it * BM + mt * 16 + qrow;
            long r1 = r0 + 8;
            if (r0 < M) {
                float4 o;
                o.x = fmaxf(acc[0] + bb.x, 0.f);
                o.y = fmaxf(acc[1] + bb.y, 0.f);
                o.z = fmaxf(acc[4] + bb.z, 0.f);
                o.w = fmaxf(acc[5] + bb.w, 0.f);
                __stcs((float4*)(out + r0 * NDIM + cbase), o);
            }
            if (r1 < M) {
                float4 o;
                o.x = fmaxf(acc[2] + bb.x, 0.f);
                o.y = fmaxf(acc[3] + bb.y, 0.f);
                o.z = fmaxf(acc[6] + bb.z, 0.f);
                o.w = fmaxf(acc[7] + bb.w, 0.f);
                __stcs((float4*)(out + r1 * NDIM + cbase), o);
            }
        }

        it = n1;
        stage = stage + 1 == 3 ? 0 : stage + 1;
    }
}

extern "C" void kernel_launch(void* const* d_in, const int* in_sizes, int n_in,
                              void* d_out, int out_size) {
    const float* x = (const float*)d_in[0];
    const float* W = (const float*)d_in[1];
    const float* b = (const float*)d_in[2];
    float* out = (float*)d_out;

    long M = (long)in_sizes[0] / KDIM;
    int ntiles = (int)((M + BM - 1) / BM);
    int grid = ntiles < MAXGRID ? ntiles : MAXGRID;

    setup_kernel<<<8, 256>>>(W);
    dense_ragged_kernel<<<grid, THREADS>>>(x, b, out, M, ntiles);
}